// round 1
// baseline (speedup 1.0000x reference)
#include <cuda_runtime.h>
#include <math.h>

#define NHID 64
#define MAXN 400000
#define MAXNEW 100000

typedef unsigned long long u64;

// ---------------- static device scratch (allocation-free rule) ----------------
__device__ float g_h [(size_t)MAXN * NHID];   // combined hidden state [N,64]
__device__ float g_mn[(size_t)MAXN * NHID];   // node messages
__device__ float g_me[(size_t)MAXN * NHID];   // edge messages
__device__ float g_t1[(size_t)MAXNEW * NHID]; // pre-BN linear output
__device__ float g_dn[MAXN];
__device__ float g_de[MAXN];
__device__ int   g_list_n[MAXN];
__device__ int   g_list_e[MAXN];
__device__ int   g_cnt[4];
__device__ float g_stats[128];                // [0:64) sum, [64:128) sumsq
__device__ float g_scale[64];
__device__ float g_shift[64];

// ---------------- small PTX helpers ----------------
__device__ __forceinline__ void fma2(u64& d, u64 a, u64 b) {
    // d.lo += a.lo*b.lo ; d.hi += a.hi*b.hi  (packed fp32x2 FMA, Blackwell)
    asm("fma.rn.f32x2 %0, %1, %2, %0;" : "+l"(d) : "l"(a), "l"(b));
}
__device__ __forceinline__ float hadd2(u64 a) {
    float lo, hi;
    asm("mov.b64 {%0, %1}, %2;" : "=f"(lo), "=f"(hi) : "l"(a));
    return lo + hi;
}
__device__ __forceinline__ u64 pack2(float lo, float hi) {
    u64 r;
    asm("mov.b64 %0, {%1, %2};" : "=l"(r) : "f"(lo), "f"(hi));
    return r;
}
__device__ __forceinline__ void red_add_v4(float* p, float4 v) {
    asm volatile("red.global.add.v4.f32 [%0], {%1, %2, %3, %4};"
                 :: "l"(p), "f"(v.x), "f"(v.y), "f"(v.z), "f"(v.w) : "memory");
}
__device__ __forceinline__ float sigmoidf_(float x) {
    return 1.f / (1.f + __expf(-x));
}

// ---------------- kernels ----------------

// Zero: g_mn, g_me, out_h region of d_out, g_dn, g_de
__global__ void zero_all_kernel(float4* __restrict__ outh, int N) {
    long A = (long)N * 16;   // float4 count of an [N,64] array
    long B = N / 4;
    long total = 3 * A + 2 * B;
    float4 z = make_float4(0.f, 0.f, 0.f, 0.f);
    for (long t = blockIdx.x * (long)blockDim.x + threadIdx.x; t < total;
         t += (long)gridDim.x * blockDim.x) {
        if      (t <     A)      ((float4*)g_mn)[t]             = z;
        else if (t < 2 * A)      ((float4*)g_me)[t - A]         = z;
        else if (t < 3 * A)      outh[t - 2 * A]                = z;
        else if (t < 3 * A + B)  ((float4*)g_dn)[t - 3 * A]     = z;
        else                     ((float4*)g_de)[t - 3 * A - B] = z;
    }
}

__global__ void zero_small_kernel() {
    int t = threadIdx.x;
    if (t < 128) g_stats[t] = 0.f;
    if (t < 4)   g_cnt[t] = 0;
}

// Diagonal extraction: dst[r] += v for entries with row==col
__global__ void diag_kernel(const int* __restrict__ rows, const int* __restrict__ cols,
                            const float* __restrict__ vals, int M, int which) {
    int e = blockIdx.x * blockDim.x + threadIdx.x;
    if (e >= M) return;
    int r = rows[e];
    if (r == cols[e]) {
        float v = vals[e];
        if (v != 0.f) atomicAdd((which ? g_de : g_dn) + r, v);
    }
}

// Compact active-row lists
__global__ void list_kernel(int N) {
    int i = blockIdx.x * blockDim.x + threadIdx.x;
    if (i >= N) return;
    if (g_dn[i] != 0.f) { int p = atomicAdd(&g_cnt[0], 1); g_list_n[p] = i; }
    if (g_de[i] != 0.f) { int p = atomicAdd(&g_cnt[1], 1); g_list_e[p] = i; }
}

// t1 = x@W1^T + b1, plus BN batch statistics (sum, sumsq per column)
__global__ void __launch_bounds__(256) t1_kernel(const float* __restrict__ x,
                                                 const float* __restrict__ W1,
                                                 const float* __restrict__ b1, int Nnew) {
    __shared__ float sW[64 * 64];
    __shared__ float sb[64];
    for (int t = threadIdx.x; t < 4096; t += 256) sW[t] = W1[t];
    if (threadIdx.x < 64) sb[threadIdx.x] = b1[threadIdx.x];
    __syncthreads();

    int row = blockIdx.x * 256 + threadIdx.x;
    bool act = row < Nnew;
    int rr = act ? row : 0;
    float xr[64];
    const float4* xp = (const float4*)(x + (size_t)rr * 64);
#pragma unroll
    for (int q = 0; q < 16; q++) {
        float4 v = xp[q];
        xr[4 * q] = v.x; xr[4 * q + 1] = v.y; xr[4 * q + 2] = v.z; xr[4 * q + 3] = v.w;
    }
    int lane = threadIdx.x & 31;
#pragma unroll 1
    for (int k0 = 0; k0 < 64; k0 += 4) {
        float out[4];
#pragma unroll
        for (int kk = 0; kk < 4; kk++) {
            const float* w = sW + (k0 + kk) * 64;
            float a = 0.f;
#pragma unroll
            for (int j = 0; j < 64; j++) a += w[j] * xr[j];
            out[kk] = a + sb[k0 + kk];
        }
        if (act)
            *(float4*)(g_t1 + (size_t)row * 64 + k0) =
                make_float4(out[0], out[1], out[2], out[3]);
#pragma unroll
        for (int kk = 0; kk < 4; kk++) {
            float v = act ? out[kk] : 0.f;
            float s = v, q = v * v;
#pragma unroll
            for (int off = 16; off; off >>= 1) {
                s += __shfl_xor_sync(~0u, s, off);
                q += __shfl_xor_sync(~0u, q, off);
            }
            if (lane == 0) {
                atomicAdd(&g_stats[k0 + kk], s);
                atomicAdd(&g_stats[64 + k0 + kk], q);
            }
        }
    }
}

__global__ void bn_kernel(const float* __restrict__ gamma, const float* __restrict__ beta,
                          int Nnew) {
    int j = threadIdx.x;
    if (j >= 64) return;
    float inv = 1.f / (float)Nnew;
    float mu = g_stats[j] * inv;
    float var = g_stats[64 + j] * inv - mu * mu;
    float rstd = rsqrtf(var + 1e-5f);
    float sc = gamma[j] * rstd;
    g_scale[j] = sc;
    g_shift[j] = beta[j] - mu * sc;
}

// t2 = relu(BN(t1)) @ W2^T + b2 ; h[Nold+row] = dn[Nold+row] * t2
__global__ void __launch_bounds__(256) t2_kernel(const float* __restrict__ W2,
                                                 const float* __restrict__ b2,
                                                 int Nnew, int Nold) {
    __shared__ float sW[64 * 64];
    __shared__ float sb[64], ssc[64], ssh[64];
    for (int t = threadIdx.x; t < 4096; t += 256) sW[t] = W2[t];
    if (threadIdx.x < 64) {
        sb[threadIdx.x] = b2[threadIdx.x];
        ssc[threadIdx.x] = g_scale[threadIdx.x];
        ssh[threadIdx.x] = g_shift[threadIdx.x];
    }
    __syncthreads();
    int row = blockIdx.x * 256 + threadIdx.x;
    if (row >= Nnew) return;
    float a[64];
    const float4* tp = (const float4*)(g_t1 + (size_t)row * 64);
#pragma unroll
    for (int q = 0; q < 16; q++) {
        float4 v = tp[q];
        a[4 * q]     = fmaxf(v.x * ssc[4 * q]     + ssh[4 * q],     0.f);
        a[4 * q + 1] = fmaxf(v.y * ssc[4 * q + 1] + ssh[4 * q + 1], 0.f);
        a[4 * q + 2] = fmaxf(v.z * ssc[4 * q + 2] + ssh[4 * q + 2], 0.f);
        a[4 * q + 3] = fmaxf(v.w * ssc[4 * q + 3] + ssh[4 * q + 3], 0.f);
    }
    int gi = Nold + row;
    float coef = g_dn[gi];
    float* hp = g_h + (size_t)gi * 64;
#pragma unroll 1
    for (int k0 = 0; k0 < 64; k0 += 4) {
        float out[4];
#pragma unroll
        for (int kk = 0; kk < 4; kk++) {
            const float* w = sW + (k0 + kk) * 64;
            float acc = 0.f;
#pragma unroll
            for (int j = 0; j < 64; j++) acc += w[j] * a[j];
            out[kk] = coef * (acc + sb[k0 + kk]);
        }
        *(float4*)(hp + k0) = make_float4(out[0], out[1], out[2], out[3]);
    }
}

__global__ void copyh_kernel(const float* __restrict__ hin, long n4) {
    long t = blockIdx.x * (long)blockDim.x + threadIdx.x;
    if (t >= n4) return;
    ((float4*)g_h)[t] = ((const float4*)hin)[t];
}

// Sparse message passing: m[r] += v * h[c] for off-diagonal entries,
// gated on the consuming mask (rows with zero coefficient never read m).
__global__ void spmm_kernel(const int* __restrict__ rows, const int* __restrict__ cols,
                            const float* __restrict__ vals, int M, int which) {
    long tid = blockIdx.x * (long)blockDim.x + threadIdx.x;
    long e = tid >> 4;
    if (e >= M) return;
    int lane = (int)(tid & 15);
    int r = rows[e], c = cols[e];
    if (r == c) return;
    float g = which ? g_de[r] : g_dn[r];
    if (g == 0.f) return;
    float v = vals[e];
    if (v == 0.f) return;
    float4 hv = *(const float4*)(g_h + (size_t)c * 64 + lane * 4);
    float* dst = (which ? g_me : g_mn) + (size_t)r * 64 + lane * 4;
    red_add_v4(dst, make_float4(v * hv.x, v * hv.y, v * hv.z, v * hv.w));
}

// Fused GRU cell over a compacted row list. Packed f32x2 math.
// outh[i] += coef[i] * GRUCell(m[i], h[i])
__global__ void __launch_bounds__(256) gru_kernel(int which,
                                                  const float* __restrict__ Wi,
                                                  const float* __restrict__ bi,
                                                  const float* __restrict__ Wh,
                                                  const float* __restrict__ bh,
                                                  float* __restrict__ outh) {
    extern __shared__ float sm[];
    float* sWi = sm;            // [192][64]
    float* sWh = sm + 12288;    // [192][64]
    float* sbi = sm + 24576;    // [192]
    float* sbh = sm + 24768;    // [192]
    for (int t = threadIdx.x; t < 12288; t += 256) { sWi[t] = Wi[t]; sWh[t] = Wh[t]; }
    for (int t = threadIdx.x; t < 192; t += 256)   { sbi[t] = bi[t]; sbh[t] = bh[t]; }
    __syncthreads();

    int cnt = g_cnt[which];
    int tid = blockIdx.x * 256 + threadIdx.x;
    if (tid >= cnt) return;
    int i = which ? g_list_e[tid] : g_list_n[tid];
    float coef = which ? g_de[i] : g_dn[i];
    const float* msrc = which ? g_me : g_mn;

    u64 mreg[32], hreg[32];
    {
        const float4* m4 = (const float4*)(msrc + (size_t)i * 64);
        const float4* h4 = (const float4*)(g_h + (size_t)i * 64);
#pragma unroll
        for (int q = 0; q < 16; q++) {
            float4 mv = m4[q];
            float4 hv = h4[q];
            mreg[2 * q]     = pack2(mv.x, mv.y);
            mreg[2 * q + 1] = pack2(mv.z, mv.w);
            hreg[2 * q]     = pack2(hv.x, hv.y);
            hreg[2 * q + 1] = pack2(hv.z, hv.w);
        }
    }

    const u64* Wi2 = (const u64*)sWi;
    const u64* Wh2 = (const u64*)sWh;

#pragma unroll 1
    for (int k0 = 0; k0 < 64; k0 += 8) {
        float hout[8];
#pragma unroll
        for (int kk = 0; kk < 8; kk++) {
            int k = k0 + kk;
            const u64* wr = Wi2 + (size_t)k * 32;
            const u64* wz = Wi2 + (size_t)(k + 64) * 32;
            const u64* wn = Wi2 + (size_t)(k + 128) * 32;
            const u64* vr = Wh2 + (size_t)k * 32;
            const u64* vz = Wh2 + (size_t)(k + 64) * 32;
            const u64* vn = Wh2 + (size_t)(k + 128) * 32;
            u64 air = 0, aiz = 0, ain = 0, ahr = 0, ahz = 0, ahn = 0;
#pragma unroll
            for (int j = 0; j < 32; j++) {
                fma2(air, wr[j], mreg[j]);
                fma2(aiz, wz[j], mreg[j]);
                fma2(ain, wn[j], mreg[j]);
                fma2(ahr, vr[j], hreg[j]);
                fma2(ahz, vz[j], hreg[j]);
                fma2(ahn, vn[j], hreg[j]);
            }
            float ir = hadd2(air) + sbi[k];
            float iz = hadd2(aiz) + sbi[k + 64];
            float in_ = hadd2(ain) + sbi[k + 128];
            float hr = hadd2(ahr) + sbh[k];
            float hz = hadd2(ahz) + sbh[k + 64];
            float hn = hadd2(ahn) + sbh[k + 128];
            float r = sigmoidf_(ir + hr);
            float z = sigmoidf_(iz + hz);
            float ng = tanhf(in_ + r * hn);
            float hk = g_h[(size_t)i * 64 + k];  // L1 hit (row just loaded)
            hout[kk] = (1.f - z) * ng + z * hk;
        }
        float* op = outh + (size_t)i * 64 + k0;
        float4 o0 = *(float4*)op;
        float4 o1 = *(float4*)(op + 4);
        o0.x += coef * hout[0]; o0.y += coef * hout[1];
        o0.z += coef * hout[2]; o0.w += coef * hout[3];
        o1.x += coef * hout[4]; o1.y += coef * hout[5];
        o1.z += coef * hout[6]; o1.w += coef * hout[7];
        *(float4*)op = o0;
        *(float4*)(op + 4) = o1;
    }
}

// Output heads: y = dn*(h_out . w_on + b_on) + de*(h_out . w_oe + b_oe)
__global__ void __launch_bounds__(256) head_kernel(const float* __restrict__ won,
                                                   const float* __restrict__ bon,
                                                   const float* __restrict__ woe,
                                                   const float* __restrict__ boe,
                                                   const float* __restrict__ outh,
                                                   float* __restrict__ outsig,
                                                   float* __restrict__ outy, int N) {
    __shared__ float s1[64], s2[64];
    if (threadIdx.x < 64) { s1[threadIdx.x] = won[threadIdx.x]; s2[threadIdx.x] = woe[threadIdx.x]; }
    __syncthreads();
    int i = blockIdx.x * 256 + threadIdx.x;
    if (i >= N) return;
    const float4* hp = (const float4*)(outh + (size_t)i * 64);
    float d1 = 0.f, d2 = 0.f;
#pragma unroll
    for (int q = 0; q < 16; q++) {
        float4 v = hp[q];
        d1 += v.x * s1[4 * q] + v.y * s1[4 * q + 1] + v.z * s1[4 * q + 2] + v.w * s1[4 * q + 3];
        d2 += v.x * s2[4 * q] + v.y * s2[4 * q + 1] + v.z * s2[4 * q + 2] + v.w * s2[4 * q + 3];
    }
    float y = g_dn[i] * (d1 + bon[0]) + g_de[i] * (d2 + boe[0]);
    outy[i] = y;
    outsig[i] = sigmoidf_(y);
}

// ---------------- launcher ----------------
extern "C" void kernel_launch(void* const* d_in, const int* in_sizes, int n_in,
                              void* d_out, int out_size) {
    const float* x    = (const float*)d_in[0];
    const float* h_in = (const float*)d_in[1];
    const int*   nrow = (const int*)d_in[2];
    const int*   ncol = (const int*)d_in[3];
    const float* nval = (const float*)d_in[4];
    const int*   erow = (const int*)d_in[5];
    const int*   ecol = (const int*)d_in[6];
    const float* eval_ = (const float*)d_in[7];
    const float* W1   = (const float*)d_in[8];
    const float* b1   = (const float*)d_in[9];
    const float* gamma= (const float*)d_in[10];
    const float* beta = (const float*)d_in[11];
    const float* W2   = (const float*)d_in[12];
    const float* b2   = (const float*)d_in[13];
    const float* Wi_n = (const float*)d_in[14];
    const float* bi_n = (const float*)d_in[15];
    const float* Wh_n = (const float*)d_in[16];
    const float* bh_n = (const float*)d_in[17];
    const float* Wi_e = (const float*)d_in[18];
    const float* bi_e = (const float*)d_in[19];
    const float* Wh_e = (const float*)d_in[20];
    const float* bh_e = (const float*)d_in[21];
    const float* w_on = (const float*)d_in[22];
    const float* b_on = (const float*)d_in[23];
    const float* w_oe = (const float*)d_in[24];
    const float* b_oe = (const float*)d_in[25];

    int Nnew = in_sizes[0] / NHID;
    int Nold = in_sizes[1] / NHID;
    int N = Nnew + Nold;
    int Mn = in_sizes[2];
    int Me = in_sizes[5];

    float* out_sig = (float*)d_out;
    float* out_y   = out_sig + N;
    float* out_h   = out_y + N;

    // opt-in >48KB dynamic smem for the GRU kernel (idempotent)
    cudaFuncSetAttribute(gru_kernel, cudaFuncAttributeMaxDynamicSharedMemorySize, 100352);

    // 1. zero scratch + h_out region
    zero_all_kernel<<<2048, 256>>>((float4*)out_h, N);
    zero_small_kernel<<<1, 256>>>();

    // 2. diagonal extraction
    diag_kernel<<<(Mn + 255) / 256, 256>>>(nrow, ncol, nval, Mn, 0);
    diag_kernel<<<(Me + 255) / 256, 256>>>(erow, ecol, eval_, Me, 1);

    // 3. compact active-row lists
    list_kernel<<<(N + 255) / 256, 256>>>(N);

    // 4. input transform
    t1_kernel<<<(Nnew + 255) / 256, 256>>>(x, W1, b1, Nnew);
    bn_kernel<<<1, 64>>>(gamma, beta, Nnew);
    t2_kernel<<<(Nnew + 255) / 256, 256>>>(W2, b2, Nnew, Nold);

    // 5. assemble h = [h_in ; dn*t2]
    long n4 = (long)Nold * 16;
    copyh_kernel<<<(int)((n4 + 255) / 256), 256>>>(h_in, n4);

    // 6. sparse message passing (gated scatter, 16 threads/entry, v4 reductions)
    long tn = (long)Mn * 16;
    long te = (long)Me * 16;
    spmm_kernel<<<(int)((tn + 255) / 256), 256>>>(nrow, ncol, nval, Mn, 0);
    spmm_kernel<<<(int)((te + 255) / 256), 256>>>(erow, ecol, eval_, Me, 1);

    // 7. GRU cells over compacted lists (packed f32x2 math)
    int gruBlocks = (N + 255) / 256;
    size_t gruSmem = (size_t)(12288 * 2 + 384) * sizeof(float);
    gru_kernel<<<gruBlocks, 256, gruSmem>>>(0, Wi_n, bi_n, Wh_n, bh_n, out_h);
    gru_kernel<<<gruBlocks, 256, gruSmem>>>(1, Wi_e, bi_e, Wh_e, bh_e, out_h);

    // 8. output heads
    head_kernel<<<(N + 255) / 256, 256>>>(w_on, b_on, w_oe, b_oe, out_h, out_sig, out_y, N);
}